// round 16
// baseline (speedup 1.0000x reference)
#include <cuda_runtime.h>

#define H 1024
#define W 1024
#define NB 16
#define TX 64
#define TY 32
#define XOFF 8          // tile col 0 at buffer x=8 (4-aligned tile columns)
#define YOFF 5
#define SX 80           // buffer row stride (floats)
#define NROWS 42        // TY + 2*5
#define NTHREADS 256
#define NSTRIP 14       // erode y-strips (18 x-chunks * 14 strips = 252 threads)
#define BUF_ELEMS (NROWS * SX)
#define SMEM_BYTES (4 * BUF_ELEMS * 4 + 8 * 8 * 4)

// accumulators: [0]=A sum skel_p*t, [1]=B sum skel_p, [2]=C sum skel_t*p, [3]=D sum skel_t,
// [4+b]=inter_b, [20+b]=sum_sig_p_b, [36+b]=sum_t_b
__device__ double g_acc[52];

__device__ __forceinline__ float ex2_approx(float x) {
    float r;
    asm("ex2.approx.ftz.f32 %0, %1;" : "=f"(r) : "f"(x));
    return r;
}
__device__ __forceinline__ float rcp_approx(float x) {
    float r;
    asm("rcp.approx.ftz.f32 %0, %1;" : "=f"(r) : "f"(x));
    return r;
}
__device__ __forceinline__ float tanh_approx(float x) {
    float r;
    asm("tanh.approx.f32 %0, %1;" : "=f"(r) : "f"(x));
    return r;
}

__device__ __forceinline__ float gelu_f(float x) {
    // tanh-form gelu with HW tanh
    float x2 = x * x;
    float y = x * fmaf(0.0356774081f, x2, 0.7978845608f);
    float hx = 0.5f * x;
    return fmaf(hx, tanh_approx(y), hx);
}

__device__ __forceinline__ float sigmoid_f(float x) {
    float den = ex2_approx(x * -1.442695041f) + 1.0f;
    return rcp_approx(den);
}

__global__ void zero_acc_kernel() {
    int i = threadIdx.x;
    if (i < 52) g_acc[i] = 0.0;
}

__device__ __forceinline__ void load_hrow(float h[4], const float* row, bool bdry, float NINF) {
    float4 c = *(const float4*)row;
    float lf = row[-1], rg = row[4];
    if (bdry) {
        lf  = (lf  < 1e30f) ? lf  : NINF;
        c.x = (c.x < 1e30f) ? c.x : NINF;
        c.y = (c.y < 1e30f) ? c.y : NINF;
        c.z = (c.z < 1e30f) ? c.z : NINF;
        c.w = (c.w < 1e30f) ? c.w : NINF;
        rg  = (rg  < 1e30f) ? rg  : NINF;
    }
    h[0] = fmaxf(lf,  fmaxf(c.x, c.y));
    h[1] = fmaxf(c.x, fmaxf(c.y, c.z));
    h[2] = fmaxf(c.y, fmaxf(c.z, c.w));
    h[3] = fmaxf(c.z, fmaxf(c.w, rg));
}

// erode (plus-min) one image's strip, rolling 3-row window, b0 -> b1
__device__ __forceinline__ void erode_img(const float* b0, float* b1, int y0, int rows,
                                          int ex4, bool bdry,
                                          int xv_lo, int xv_hi, int yv_lo, int yv_hi,
                                          float INF) {
    if (rows <= 0) return;
    const float* pbase = b0 + y0 * SX + ex4;
    float4 uc = *(const float4*)(pbase - SX);
    float4 pc = *(const float4*)pbase;
    float pl = pbase[-1], pr = pbase[4];
    #pragma unroll 1
    for (int r = 0; r < rows; ++r) {
        const float* nrow = b0 + (y0 + r + 1) * SX + ex4;
        float4 nc = *(const float4*)nrow;
        float nl = nrow[-1], nr2 = nrow[4];
        float4 o;
        o.x = fminf(fminf(pc.x, fminf(pl,   pc.y)), fminf(uc.x, nc.x));
        o.y = fminf(fminf(pc.y, fminf(pc.x, pc.z)), fminf(uc.y, nc.y));
        o.z = fminf(fminf(pc.z, fminf(pc.y, pc.w)), fminf(uc.z, nc.z));
        o.w = fminf(fminf(pc.w, fminf(pc.z, pr  )), fminf(uc.w, nc.w));
        int y = y0 + r;
        if (bdry) {
            bool yok = (y >= yv_lo) & (y <= yv_hi);
            o.x = (yok & (ex4 + 0 >= xv_lo) & (ex4 + 0 <= xv_hi)) ? o.x : INF;
            o.y = (yok & (ex4 + 1 >= xv_lo) & (ex4 + 1 <= xv_hi)) ? o.y : INF;
            o.z = (yok & (ex4 + 2 >= xv_lo) & (ex4 + 2 <= xv_hi)) ? o.z : INF;
            o.w = (yok & (ex4 + 3 >= xv_lo) & (ex4 + 3 <= xv_hi)) ? o.w : INF;
        }
        *(float4*)(b1 + y * SX + ex4) = o;
        uc = pc; pc = nc; pl = nl; pr = nr2;
    }
}

// dilate 3x3 + delta + skel update for one image's 2x4 block
__device__ __forceinline__ void dilate_update(const float* b0, const float* b1,
                                              int sx, int sy, bool bdry, float NINF,
                                              float* skel, int lvl) {
    float h0[4], h1[4], h2[4], h3[4];
    load_hrow(h0, b1 + (sy - 1) * SX + sx, bdry, NINF);
    load_hrow(h1, b1 + (sy    ) * SX + sx, bdry, NINF);
    load_hrow(h2, b1 + (sy + 1) * SX + sx, bdry, NINF);
    load_hrow(h3, b1 + (sy + 2) * SX + sx, bdry, NINF);
    #pragma unroll
    for (int r = 0; r < 2; ++r) {
        const float4 a4 = *(const float4*)(b0 + (sy + r) * SX + sx);
        float av[4] = {a4.x, a4.y, a4.z, a4.w};
        #pragma unroll
        for (int c = 0; c < 4; ++c) {
            float m = (r == 0) ? fmaxf(h0[c], fmaxf(h1[c], h2[c]))
                               : fmaxf(h1[c], fmaxf(h2[c], h3[c]));
            float delta = gelu_f(av[c] - m);
            int j = r * 4 + c;
            if (lvl == 0) skel[j] = delta;
            else          skel[j] += gelu_f(delta - skel[j] * delta);
        }
    }
}

__global__ __launch_bounds__(NTHREADS, 4)
void cldice_main(const float* __restrict__ y_pred, const float* __restrict__ y_true) {
    extern __shared__ float sm[];
    float* bufPA = sm;
    float* bufPB = sm + BUF_ELEMS;
    float* bufTA = sm + 2 * BUF_ELEMS;
    float* bufTB = sm + 3 * BUF_ELEMS;
    float (*red)[8] = (float(*)[8])(sm + 4 * BUF_ELEMS);

    const int tid = threadIdx.x;
    const int gx0 = blockIdx.x * TX, gy0 = blockIdx.y * TY, b = blockIdx.z;
    const int base = b * (H * W);
    const bool bdry = (blockIdx.x == 0) | (blockIdx.x == (W/TX - 1)) |
                      (blockIdx.y == 0) | (blockIdx.y == (H/TY - 1));

    // 2x4 output block per thread: 16 blocks in x, 16 in y
    const int tx4 = tid & 15, ty2 = tid >> 4;
    const int sx = XOFF + tx4 * 4, sy = YOFF + ty2 * 2;

    const int xv_lo = XOFF - gx0;
    const int xv_hi = XOFF + (W - 1) - gx0;
    const int yv_lo = YOFF - gy0;
    const int yv_hi = YOFF + (H - 1) - gy0;

    // erode strip mapping: 18 x-chunks * 14 y-strips
    const int ys = tid / 18;
    const int xc = tid - ys * 18;
    const int ex4 = 4 + xc * 4;

    // vector-load mapping: 20 float4-chunks per 80-wide row
    const int vy0 = tid / 20;
    const int vx0 = tid - vy0 * 20;

    float skel_p[8], skel_t[8];
    float accA = 0.f, accB = 0.f, accC = 0.f, accD = 0.f;
    float accI = 0.f, accP = 0.f, accT = 0.f;

    const float INF = __int_as_float(0x7f800000);
    const float NINF = __int_as_float(0xff800000);

    // ---- load halo tiles for both images ----
    if (!bdry) {
        const float* gp = y_pred + base + (gy0 - YOFF) * W + gx0 - XOFF;
        const float* gt = y_true + base + (gy0 - YOFF) * W + gx0 - XOFF;
        int y = vy0, x = vx0;
        while (y < NROWS) {
            *(float4*)(bufPA + y * SX + x * 4) = *(const float4*)(gp + y * W + x * 4);
            *(float4*)(bufTA + y * SX + x * 4) = *(const float4*)(gt + y * W + x * 4);
            x += 16; y += 12;
            if (x >= 20) { x -= 20; y += 1; }
        }
    } else {
        for (int i = tid; i < NROWS * 74; i += NTHREADS) {
            int yy = i / 74, xx = i - yy * 74;
            int x = xx + 3;
            int gy = gy0 + yy - YOFF, gx = gx0 + x - XOFF;
            bool ok = (gy >= 0) & (gy < H) & (gx >= 0) & (gx < W);
            int off = base + gy * W + gx;
            bufPA[yy * SX + x] = ok ? __ldg(y_pred + off) : INF;
            bufTA[yy * SX + x] = ok ? __ldg(y_true + off) : INF;
        }
    }
    __syncthreads();

    float* p0 = bufPA; float* p1 = bufPB;
    float* t0 = bufTA; float* t1 = bufTB;

    #pragma unroll 1
    for (int lvl = 0; lvl < 4; ++lvl) {
        if (lvl) __syncthreads();   // protect prior dilate's b0 reads from this erode's writes

        // ---- erode both images ----
        const int yl = 1 + lvl;
        const int ny = 40 - 2 * lvl;
        int rows = 0, y0 = 0;
        if (ys < NSTRIP) {
            int bse = ny / NSTRIP, rem = ny - bse * NSTRIP;
            rows = bse + (ys < rem ? 1 : 0);
            y0 = yl + ys * bse + (ys < rem ? ys : rem);
        }
        erode_img(p0, p1, y0, rows, ex4, bdry, xv_lo, xv_hi, yv_lo, yv_hi, INF);
        erode_img(t0, t1, y0, rows, ex4, bdry, xv_lo, xv_hi, yv_lo, yv_hi, INF);
        __syncthreads();

        // ---- dilate + skel update, both images ----
        dilate_update(p0, p1, sx, sy, bdry, NINF, skel_p, lvl);
        dilate_update(t0, t1, sx, sy, bdry, NINF, skel_t, lvl);

        float* tmp = p0; p0 = p1; p1 = tmp;
        tmp = t0; t0 = t1; t1 = tmp;
    }

    // ---- epilogue: all 7 reduction terms; each gmem value read once ----
    #pragma unroll
    for (int r = 0; r < 2; ++r) {
        const int goff = base + (gy0 + sy - YOFF + r) * W + gx0 + sx - XOFF;
        const float4 t4 = *(const float4*)(y_true + goff);
        const float4 q4 = *(const float4*)(y_pred + goff);
        float tvv[4] = {t4.x, t4.y, t4.z, t4.w};
        float qvv[4] = {q4.x, q4.y, q4.z, q4.w};
        #pragma unroll
        for (int c = 0; c < 4; ++c) {
            int j = r * 4 + c;
            accA += skel_p[j] * tvv[c];
            accB += skel_p[j];
            accC += skel_t[j] * qvv[c];
            accD += skel_t[j];
            float s = sigmoid_f(qvv[c]);
            accI += s * tvv[c];
            accP += s;
            accT += tvv[c];
        }
    }

    // ---- block reduction of 7 partials, then one double atomic each ----
    float vals[7] = {accA, accB, accC, accD, accI, accP, accT};
    int lane = tid & 31, warp = tid >> 5;
    #pragma unroll
    for (int k = 0; k < 7; ++k) {
        float v = vals[k];
        #pragma unroll
        for (int o = 16; o > 0; o >>= 1) v += __shfl_down_sync(0xffffffffu, v, o);
        if (lane == 0) red[warp][k] = v;
    }
    __syncthreads();
    if (warp == 0 && lane < 7) {
        float s = 0.f;
        #pragma unroll
        for (int w = 0; w < 8; ++w) s += red[w][lane];
        int idx = (lane < 4) ? lane : (4 + (lane - 4) * 16 + b);
        atomicAdd(&g_acc[idx], (double)s);
    }
}

__global__ void finalize_kernel(float* out, int n) {
    if (threadIdx.x == 0) {
        double A = g_acc[0], B = g_acc[1], C = g_acc[2], D = g_acc[3];
        double tprec = (A + 1.0) / (B + 1.0);
        double tsens = (C + 1.0) / (D + 1.0);
        double cl = 1.0 - 2.0 * (tprec * tsens) / (tprec + tsens);
        double dsum = 0.0;
        for (int i = 0; i < 16; ++i) {
            double gd = (2.0 * g_acc[4 + i] + 1e-4) / (g_acc[20 + i] + g_acc[36 + i] + 1e-4);
            dsum += 1.0 - gd;
        }
        double dice = dsum / 16.0;
        double res = 0.5 * cl + 0.5 * dice;
        for (int i = 0; i < n; ++i) out[i] = (float)res;
    }
}

extern "C" void kernel_launch(void* const* d_in, const int* in_sizes, int n_in,
                              void* d_out, int out_size) {
    const float* y_pred = (const float*)d_in[0];
    const float* y_true = (const float*)d_in[1];
    (void)in_sizes; (void)n_in;

    cudaFuncSetAttribute(cldice_main, cudaFuncAttributeMaxDynamicSharedMemorySize, SMEM_BYTES);

    zero_acc_kernel<<<1, 64>>>();
    dim3 grid(W / TX, H / TY, NB);
    cldice_main<<<grid, NTHREADS, SMEM_BYTES>>>(y_pred, y_true);
    finalize_kernel<<<1, 32>>>((float*)d_out, out_size);
}